// round 1
// baseline (speedup 1.0000x reference)
#include <cuda_runtime.h>

#define NN 100000
#define DD 256
#define EE 300000

typedef unsigned long long ull;

// ---------------- scratch (module-load allocations; allowed) ----------------
__device__ float g_acc[NN * DD];     // scatter-sum accumulator
__device__ float g_x1[NN * DD];      // layer-1 output
__device__ float g_x2[NN * DD];      // layer-2 output
__device__ float g_deg[NN];
__device__ float g_invdeg[NN];
__device__ int   g_src[EE];
__device__ int   g_dst[EE];
__device__ int   g_is64;

// ---------------- index dtype detection + conversion ----------------
__global__ void detect_kernel(const unsigned int* __restrict__ w) {
    if (threadIdx.x == 0 && blockIdx.x == 0) {
        unsigned int s = 0;
        #pragma unroll 1
        for (int i = 1; i < 256; i += 2) s |= w[i];   // high halves if int64
        g_is64 = (s == 0u) ? 1 : 0;
    }
}

__global__ void convert_kernel(const void* __restrict__ edge) {
    int e = blockIdx.x * blockDim.x + threadIdx.x;
    if (e >= EE) return;
    if (g_is64) {
        const long long* p = (const long long*)edge;
        g_src[e] = (int)p[e];
        g_dst[e] = (int)p[EE + e];
    } else {
        const int* p = (const int*)edge;
        g_src[e] = p[e];
        g_dst[e] = p[EE + e];
    }
}

// ---------------- degree ----------------
__global__ void zero_deg_kernel() {
    int n = blockIdx.x * blockDim.x + threadIdx.x;
    if (n < NN) g_deg[n] = 0.f;
}

__global__ void deg_kernel() {
    int e = blockIdx.x * blockDim.x + threadIdx.x;
    if (e < EE) atomicAdd(&g_deg[g_dst[e]], 1.0f);
}

__global__ void invdeg_kernel() {
    int n = blockIdx.x * blockDim.x + threadIdx.x;
    if (n < NN) g_invdeg[n] = 1.0f / fmaxf(g_deg[n], 1.0f);
}

// ---------------- per-layer aggregation ----------------
__global__ void zero_acc_kernel() {
    int i = blockIdx.x * blockDim.x + threadIdx.x;
    if (i < NN * DD / 4) ((float4*)g_acc)[i] = make_float4(0.f, 0.f, 0.f, 0.f);
}

// one thread per (edge, 4-float chunk): coalesced gather + scatter atomics
__global__ void scatter_kernel(const float* __restrict__ xext, int xsel) {
    const float* xin = (xsel == 0) ? xext : ((xsel == 1) ? g_x1 : g_x2);
    int i = blockIdx.x * blockDim.x + threadIdx.x;
    if (i >= EE * 64) return;
    int e = i >> 6;
    int c = (i & 63) << 2;
    int s = g_src[e];
    int d = g_dst[e];
    float4 v = *(const float4*)(xin + (size_t)s * DD + c);
    float* a = g_acc + (size_t)d * DD + c;
    atomicAdd(a + 0, v.x);
    atomicAdd(a + 1, v.y);
    atomicAdd(a + 2, v.z);
    atomicAdd(a + 3, v.w);
}

// ---------------- packed-f32x2 helpers (2 FMA lanes / instr on sm_103a) ----------------
__device__ __forceinline__ ull pk(float x, float y) {
    ull r; asm("mov.b64 %0,{%1,%2};" : "=l"(r) : "f"(x), "f"(y)); return r;
}
__device__ __forceinline__ void upk(ull v, float& x, float& y) {
    asm("mov.b64 {%0,%1},%2;" : "=f"(x), "=f"(y) : "l"(v));
}
__device__ __forceinline__ void fma2(ull& d, ull a, ull b) {
    asm("fma.rn.f32x2 %0,%1,%2,%0;" : "+l"(d) : "l"(a), "l"(b));
}

// ---------------- fused layer GEMM ----------------
// out[n, m] = relu?( sum_k acc[n,k]*invdeg[n]*Wl[m,k] + sum_k xin[n,k]*Wr[m,k] + b[m] )
// Treated as [N x 512] @ [512 x 256]^T ; A cols 0..255 = invdeg*acc, 256..511 = xin.
__global__ __launch_bounds__(256, 2) void gemm_kernel(
    const float* __restrict__ xext, int xsel,
    float* __restrict__ oext, int osel,
    const float* __restrict__ Wl, const float* __restrict__ Wr,
    const float* __restrict__ bias, int do_relu)
{
    const float* xin = (xsel == 0) ? xext : ((xsel == 1) ? g_x1 : g_x2);
    float* out = (osel == 0) ? oext : ((osel == 1) ? g_x1 : g_x2);

    __shared__ float As[8][128];
    __shared__ float Bs[8][128];

    const int row0 = blockIdx.x * 128;
    const int m0 = blockIdx.y * 128;
    const int tid = threadIdx.x;
    const int lrow = tid >> 1;          // 0..127 (load row)
    const int lk4 = (tid & 1) * 4;      // 0 or 4 (load k-offset)
    const int tx = tid & 15;            // col group
    const int ty = tid >> 4;            // row group

    ull acc[8][4];
    #pragma unroll
    for (int i = 0; i < 8; i++)
        #pragma unroll
        for (int j = 0; j < 4; j++) acc[i][j] = 0ull;

    const int grow = row0 + lrow;
    const bool rok = grow < NN;
    const float invd = rok ? g_invdeg[grow] : 0.f;

    auto loadA = [&](int k0) -> float4 {
        float4 v = make_float4(0.f, 0.f, 0.f, 0.f);
        if (rok) {
            if (k0 < 256) {
                v = *(const float4*)(g_acc + (size_t)grow * DD + k0 + lk4);
                v.x *= invd; v.y *= invd; v.z *= invd; v.w *= invd;
            } else {
                v = *(const float4*)(xin + (size_t)grow * DD + (k0 - 256) + lk4);
            }
        }
        return v;
    };
    auto loadB = [&](int k0) -> float4 {
        const float* W = (k0 < 256) ? Wl : Wr;
        return *(const float4*)(W + (size_t)(m0 + lrow) * 256 + (k0 & 255) + lk4);
    };

    float4 av = loadA(0);
    float4 bv = loadB(0);

    for (int k0 = 0; k0 < 512; k0 += 8) {
        __syncthreads();
        As[lk4 + 0][lrow] = av.x;
        As[lk4 + 1][lrow] = av.y;
        As[lk4 + 2][lrow] = av.z;
        As[lk4 + 3][lrow] = av.w;
        Bs[lk4 + 0][lrow] = bv.x;
        Bs[lk4 + 1][lrow] = bv.y;
        Bs[lk4 + 2][lrow] = bv.z;
        Bs[lk4 + 3][lrow] = bv.w;
        __syncthreads();
        if (k0 + 8 < 512) {   // prefetch next tile; overlaps with compute below
            av = loadA(k0 + 8);
            bv = loadB(k0 + 8);
        }
        #pragma unroll
        for (int kk = 0; kk < 8; kk++) {
            float4 a0 = *(const float4*)&As[kk][ty * 8];
            float4 a1 = *(const float4*)&As[kk][ty * 8 + 4];
            float4 b0 = *(const float4*)&Bs[kk][tx * 8];
            float4 b1 = *(const float4*)&Bs[kk][tx * 8 + 4];
            ull bp0 = pk(b0.x, b0.y), bp1 = pk(b0.z, b0.w);
            ull bp2 = pk(b1.x, b1.y), bp3 = pk(b1.z, b1.w);
            float aa[8] = {a0.x, a0.y, a0.z, a0.w, a1.x, a1.y, a1.z, a1.w};
            #pragma unroll
            for (int i = 0; i < 8; i++) {
                ull ap = pk(aa[i], aa[i]);
                fma2(acc[i][0], ap, bp0);
                fma2(acc[i][1], ap, bp1);
                fma2(acc[i][2], ap, bp2);
                fma2(acc[i][3], ap, bp3);
            }
        }
    }

    #pragma unroll
    for (int i = 0; i < 8; i++) {
        int r = row0 + ty * 8 + i;
        if (r < NN) {
            #pragma unroll
            for (int j = 0; j < 4; j++) {
                float v0, v1;
                upk(acc[i][j], v0, v1);
                int c0 = m0 + tx * 8 + j * 2;
                v0 += bias[c0];
                v1 += bias[c0 + 1];
                if (do_relu) { v0 = fmaxf(v0, 0.f); v1 = fmaxf(v1, 0.f); }
                *(float2*)(out + (size_t)r * DD + c0) = make_float2(v0, v1);
            }
        }
    }
}

// ---------------- launcher ----------------
extern "C" void kernel_launch(void* const* d_in, const int* in_sizes, int n_in,
                              void* d_out, int out_size) {
    (void)in_sizes; (void)n_in; (void)out_size;
    const void* edge = d_in[0];
    const float* x0 = (const float*)d_in[1];
    const float* Wl[3] = {(const float*)d_in[2], (const float*)d_in[5], (const float*)d_in[8]};
    const float* Wr[3] = {(const float*)d_in[3], (const float*)d_in[6], (const float*)d_in[9]};
    const float* bb[3] = {(const float*)d_in[4], (const float*)d_in[7], (const float*)d_in[10]};
    float* out = (float*)d_out;

    const int TB = 256;
    const int ecnt = (EE + TB - 1) / TB;
    const int ncnt = (NN + TB - 1) / TB;
    const int zcnt = (NN * DD / 4 + TB - 1) / TB;
    const int scnt = (EE * 64 + TB - 1) / TB;
    dim3 ggrid((NN + 127) / 128, 2);

    detect_kernel<<<1, 32>>>((const unsigned int*)edge);
    convert_kernel<<<ecnt, TB>>>(edge);
    zero_deg_kernel<<<ncnt, TB>>>();
    deg_kernel<<<ecnt, TB>>>();
    invdeg_kernel<<<ncnt, TB>>>();

    // layer 1: in = x_all (external), out = g_x1, relu
    zero_acc_kernel<<<zcnt, TB>>>();
    scatter_kernel<<<scnt, TB>>>(x0, 0);
    gemm_kernel<<<ggrid, TB>>>(x0, 0, nullptr, 1, Wl[0], Wr[0], bb[0], 1);

    // layer 2: in = g_x1, out = g_x2, relu
    zero_acc_kernel<<<zcnt, TB>>>();
    scatter_kernel<<<scnt, TB>>>(nullptr, 1);
    gemm_kernel<<<ggrid, TB>>>(nullptr, 1, nullptr, 2, Wl[1], Wr[1], bb[1], 1);

    // layer 3: in = g_x2, out = d_out, no relu
    zero_acc_kernel<<<zcnt, TB>>>();
    scatter_kernel<<<scnt, TB>>>(nullptr, 2);
    gemm_kernel<<<ggrid, TB>>>(nullptr, 2, out, 0, Wl[2], Wr[2], bb[2], 0);
}

// round 3
// speedup vs baseline: 1.8516x; 1.8516x over previous
#include <cuda_runtime.h>
#include <cuda_bf16.h>

#define NN 100000
#define DD 256
#define EE 300000

typedef unsigned long long ull;

// ---------------- scratch ----------------
__device__ __align__(16) float g_acc[NN * DD];
__device__ __align__(16) float g_x1[NN * DD];
__device__ __align__(16) float g_x2[NN * DD];
__device__ float g_deg[NN];
__device__ float g_invdeg[NN];
__device__ int   g_src[EE];
__device__ int   g_dst[EE];
__device__ int   g_is64;
__device__ __align__(16) __nv_bfloat16 g_bhi[256 * 512];  // W split hi: [m][k], k-major
__device__ __align__(16) __nv_bfloat16 g_blo[256 * 512];  // W split lo

// ---------------- index dtype detection + conversion ----------------
__global__ void detect_kernel(const unsigned int* __restrict__ w) {
    if (threadIdx.x == 0 && blockIdx.x == 0) {
        unsigned int s = 0;
        #pragma unroll 1
        for (int i = 1; i < 256; i += 2) s |= w[i];
        g_is64 = (s == 0u) ? 1 : 0;
    }
}

__global__ void convert_kernel(const void* __restrict__ edge) {
    int e = blockIdx.x * blockDim.x + threadIdx.x;
    if (e >= EE) return;
    if (g_is64) {
        const long long* p = (const long long*)edge;
        g_src[e] = (int)p[e];
        g_dst[e] = (int)p[EE + e];
    } else {
        const int* p = (const int*)edge;
        g_src[e] = p[e];
        g_dst[e] = p[EE + e];
    }
}

// ---------------- degree ----------------
__global__ void zero_deg_kernel() {
    int n = blockIdx.x * blockDim.x + threadIdx.x;
    if (n < NN) g_deg[n] = 0.f;
}
__global__ void deg_kernel() {
    int e = blockIdx.x * blockDim.x + threadIdx.x;
    if (e < EE) atomicAdd(&g_deg[g_dst[e]], 1.0f);
}
__global__ void invdeg_kernel() {
    int n = blockIdx.x * blockDim.x + threadIdx.x;
    if (n < NN) g_invdeg[n] = 1.0f / fmaxf(g_deg[n], 1.0f);
}

// ---------------- aggregation ----------------
__global__ void zero_acc_kernel() {
    int i = blockIdx.x * blockDim.x + threadIdx.x;
    if (i < NN * DD / 4) ((float4*)g_acc)[i] = make_float4(0.f, 0.f, 0.f, 0.f);
}

__global__ void scatter_kernel(const float* __restrict__ xext, int xsel) {
    const float* xin = (xsel == 0) ? xext : ((xsel == 1) ? g_x1 : g_x2);
    int i = blockIdx.x * blockDim.x + threadIdx.x;
    if (i >= EE * 64) return;
    int e = i >> 6;
    int c = (i & 63) << 2;
    int s = g_src[e];
    int d = g_dst[e];
    float4 v = *(const float4*)(xin + (size_t)s * DD + c);
    float* a = g_acc + (size_t)d * DD + c;
    atomicAdd(a + 0, v.x);
    atomicAdd(a + 1, v.y);
    atomicAdd(a + 2, v.z);
    atomicAdd(a + 3, v.w);
}

// ---------------- weight split (fp32 -> bf16 hi/lo) ----------------
__global__ void convw_kernel(const float* __restrict__ Wl, const float* __restrict__ Wr) {
    int i = blockIdx.x * blockDim.x + threadIdx.x;
    if (i >= 256 * 512) return;
    int m = i >> 9, k = i & 511;
    float w = (k < 256) ? Wl[m * 256 + k] : Wr[m * 256 + (k - 256)];
    __nv_bfloat16 h = __float2bfloat16(w);
    float lo = w - __bfloat162float(h);
    g_bhi[i] = h;
    g_blo[i] = __float2bfloat16(lo);
}

// ---------------- mma helpers (baseline PTX, compiles at compute_103) ----------------
__device__ __forceinline__ unsigned sm_u32(const void* p) {
    unsigned r;
    asm("{ .reg .u64 t; cvta.to.shared.u64 t, %1; cvt.u32.u64 %0, t; }" : "=r"(r) : "l"(p));
    return r;
}
__device__ __forceinline__ void sts128(unsigned a, unsigned x, unsigned y, unsigned z, unsigned w) {
    asm volatile("st.shared.v4.b32 [%0], {%1,%2,%3,%4};" :: "r"(a), "r"(x), "r"(y), "r"(z), "r"(w));
}
__device__ __forceinline__ void ldsm4(unsigned& r0, unsigned& r1, unsigned& r2, unsigned& r3, unsigned a) {
    asm volatile("ldmatrix.sync.aligned.m8n8.x4.shared.b16 {%0,%1,%2,%3}, [%4];"
                 : "=r"(r0), "=r"(r1), "=r"(r2), "=r"(r3) : "r"(a));
}
__device__ __forceinline__ void mma16816(float* c, const unsigned* a, unsigned b0, unsigned b1) {
    asm volatile(
        "mma.sync.aligned.m16n8k16.row.col.f32.bf16.bf16.f32 "
        "{%0,%1,%2,%3}, {%4,%5,%6,%7}, {%8,%9}, {%0,%1,%2,%3};"
        : "+f"(c[0]), "+f"(c[1]), "+f"(c[2]), "+f"(c[3])
        : "r"(a[0]), "r"(a[1]), "r"(a[2]), "r"(a[3]), "r"(b0), "r"(b1));
}
__device__ __forceinline__ unsigned b2u(__nv_bfloat162 v) {
    unsigned r;
    memcpy(&r, &v, 4);
    return r;
}

// smem layout: rows padded to 80B (gcd(80,128)=16 -> conflict-free ldmatrix)
#define ASTR 80
#define SM_A 10240            // 128 rows * 80B
#define SM_B 20480            // 256 rows * 80B
#define SM_TOT (2*SM_A + 2*SM_B)   // AH | AL | BH | BL  = 61440 B

// ---------------- fused layer GEMM (mma.sync bf16, 2-term split) ----------------
// out[r, m] = relu?( sum_k A[r,k] * W[m,k] + b[m] ), A = [invdeg*acc | xin] (K=512)
__global__ __launch_bounds__(512) void gemm_mma_kernel(
    const float* __restrict__ xext, int xsel,
    float* __restrict__ oext, int osel,
    const float* __restrict__ bias, int do_relu)
{
    extern __shared__ char smem[];
    const float* xin = (xsel == 0) ? xext : ((xsel == 1) ? g_x1 : g_x2);
    float* out = (osel == 0) ? oext : ((osel == 1) ? g_x1 : g_x2);

    const unsigned su = sm_u32(smem);
    const unsigned suAH = su;
    const unsigned suAL = su + SM_A;
    const unsigned suBH = su + 2 * SM_A;
    const unsigned suBL = su + 2 * SM_A + SM_B;

    const int tid = threadIdx.x;
    const int wid = tid >> 5;
    const int lane = tid & 31;
    const int wm = wid & 1;        // 2 warps over M (64 rows each)
    const int wn = wid >> 1;       // 8 warps over N (32 cols each)
    const int row0 = blockIdx.x * 128;

    // --- loader geometry ---
    const int arow = tid >> 2;            // 0..127
    const int akq = tid & 3;              // k-octet within 32-chunk
    const int gr = row0 + arow;
    const bool rok = gr < NN;
    const float invd = rok ? g_invdeg[gr] : 0.f;
    const float* aggrow = g_acc + (size_t)(rok ? gr : 0) * DD;
    const float* xrow = xin + (size_t)(rok ? gr : 0) * DD;

    const int brow = tid >> 1;            // 0..255
    const int bkh = (tid & 1) * 16;       // bf16 elems

    // --- ldmatrix fragment addresses ---
    const unsigned aoff = (unsigned)((wm * 64 + (lane & 15)) * ASTR + (lane >> 4) * 16);
    const unsigned boff = (unsigned)((wn * 32 + ((lane >> 4) & 1) * 8 + (lane & 7)) * ASTR
                                     + ((lane >> 3) & 1) * 16);

    float acc[4][4][4];
    #pragma unroll
    for (int i = 0; i < 4; i++)
        #pragma unroll
        for (int j = 0; j < 4; j++)
            #pragma unroll
            for (int q = 0; q < 4; q++) acc[i][j][q] = 0.f;

    float4 pa0, pa1;
    uint4 pbh0, pbh1, pbl0, pbl1;
    float psc;

    auto loadCk = [&](int ck) {
        const int side = ck >> 3;
        const float* s = (side ? xrow : aggrow) + (ck & 7) * 32 + akq * 8;
        psc = side ? 1.f : invd;
        if (rok) {
            pa0 = *(const float4*)(s);
            pa1 = *(const float4*)(s + 4);
        } else {
            pa0 = make_float4(0.f, 0.f, 0.f, 0.f);
            pa1 = pa0;
        }
        size_t go = (size_t)brow * 512 + ck * 32 + bkh;
        pbh0 = *(const uint4*)(g_bhi + go);
        pbh1 = *(const uint4*)(g_bhi + go + 8);
        pbl0 = *(const uint4*)(g_blo + go);
        pbl1 = *(const uint4*)(g_blo + go + 8);
    };

    loadCk(0);

    #pragma unroll 1
    for (int ck = 0; ck < 16; ck++) {
        __syncthreads();
        // ---- store A (convert fp32 -> bf16 hi/lo with scale) ----
        {
            float v[8] = {pa0.x * psc, pa0.y * psc, pa0.z * psc, pa0.w * psc,
                          pa1.x * psc, pa1.y * psc, pa1.z * psc, pa1.w * psc};
            unsigned h[4], l[4];
            #pragma unroll
            for (int i = 0; i < 4; i++) {
                __nv_bfloat162 hh = __floats2bfloat162_rn(v[2 * i], v[2 * i + 1]);
                float lx = v[2 * i] - __bfloat162float(hh.x);
                float ly = v[2 * i + 1] - __bfloat162float(hh.y);
                __nv_bfloat162 ll = __floats2bfloat162_rn(lx, ly);
                h[i] = b2u(hh);
                l[i] = b2u(ll);
            }
            unsigned off = (unsigned)(arow * ASTR + akq * 16);
            sts128(suAH + off, h[0], h[1], h[2], h[3]);
            sts128(suAL + off, l[0], l[1], l[2], l[3]);
        }
        // ---- store B ----
        {
            unsigned off = (unsigned)(brow * ASTR + bkh * 2);
            sts128(suBH + off, pbh0.x, pbh0.y, pbh0.z, pbh0.w);
            sts128(suBH + off + 16, pbh1.x, pbh1.y, pbh1.z, pbh1.w);
            sts128(suBL + off, pbl0.x, pbl0.y, pbl0.z, pbl0.w);
            sts128(suBL + off + 16, pbl1.x, pbl1.y, pbl1.z, pbl1.w);
        }
        __syncthreads();
        if (ck < 15) loadCk(ck + 1);   // overlap gmem with MMA below

        // ---- compute on this chunk: 2 x k16 steps ----
        #pragma unroll
        for (int ks = 0; ks < 2; ks++) {
            const unsigned kb = (unsigned)(ks * 32);
            unsigned bh[4][2], bl[4][2];
            #pragma unroll
            for (int p = 0; p < 2; p++) {
                ldsm4(bh[2 * p][0], bh[2 * p][1], bh[2 * p + 1][0], bh[2 * p + 1][1],
                      suBH + boff + p * (16 * ASTR) + kb);
                ldsm4(bl[2 * p][0], bl[2 * p][1], bl[2 * p + 1][0], bl[2 * p + 1][1],
                      suBL + boff + p * (16 * ASTR) + kb);
            }
            #pragma unroll
            for (int mi = 0; mi < 4; mi++) {
                unsigned af[4];
                ldsm4(af[0], af[1], af[2], af[3], suAH + aoff + mi * (16 * ASTR) + kb);
                #pragma unroll
                for (int ni = 0; ni < 4; ni++) mma16816(acc[mi][ni], af, bh[ni][0], bh[ni][1]);
                #pragma unroll
                for (int ni = 0; ni < 4; ni++) mma16816(acc[mi][ni], af, bl[ni][0], bl[ni][1]);
                ldsm4(af[0], af[1], af[2], af[3], suAL + aoff + mi * (16 * ASTR) + kb);
                #pragma unroll
                for (int ni = 0; ni < 4; ni++) mma16816(acc[mi][ni], af, bh[ni][0], bh[ni][1]);
            }
        }
    }

    // ---- epilogue: bias + relu, direct gmem stores ----
    const int gr2 = lane >> 2;
    const int gc2 = (lane & 3) * 2;
    #pragma unroll
    for (int mi = 0; mi < 4; mi++) {
        const int rbase = row0 + wm * 64 + mi * 16 + gr2;
        #pragma unroll
        for (int h = 0; h < 2; h++) {
            const int r = rbase + h * 8;
            if (r < NN) {
                float* orow = out + (size_t)r * DD;
                #pragma unroll
                for (int ni = 0; ni < 4; ni++) {
                    const int c = wn * 32 + ni * 8 + gc2;
                    float2 bv = *(const float2*)(bias + c);
                    float v0 = acc[mi][ni][h * 2 + 0] + bv.x;
                    float v1 = acc[mi][ni][h * 2 + 1] + bv.y;
                    if (do_relu) { v0 = fmaxf(v0, 0.f); v1 = fmaxf(v1, 0.f); }
                    *(float2*)(orow + c) = make_float2(v0, v1);
                }
            }
        }
    }
}

// ---------------- launcher ----------------
extern "C" void kernel_launch(void* const* d_in, const int* in_sizes, int n_in,
                              void* d_out, int out_size) {
    (void)in_sizes; (void)n_in; (void)out_size;
    const void* edge = d_in[0];
    const float* x0 = (const float*)d_in[1];
    const float* Wl[3] = {(const float*)d_in[2], (const float*)d_in[5], (const float*)d_in[8]};
    const float* Wr[3] = {(const float*)d_in[3], (const float*)d_in[6], (const float*)d_in[9]};
    const float* bb[3] = {(const float*)d_in[4], (const float*)d_in[7], (const float*)d_in[10]};
    float* out = (float*)d_out;

    static int smem_set = 0;
    if (!smem_set) {
        cudaFuncSetAttribute(gemm_mma_kernel, cudaFuncAttributeMaxDynamicSharedMemorySize, SM_TOT);
        smem_set = 1;
    }

    const int TB = 256;
    const int ecnt = (EE + TB - 1) / TB;
    const int ncnt = (NN + TB - 1) / TB;
    const int zcnt = (NN * DD / 4 + TB - 1) / TB;
    const int scnt = (EE * 64 + TB - 1) / TB;
    const int wcnt = (256 * 512 + TB - 1) / TB;
    const int ggrid = (NN + 127) / 128;

    detect_kernel<<<1, 32>>>((const unsigned int*)edge);
    convert_kernel<<<ecnt, TB>>>(edge);
    zero_deg_kernel<<<ncnt, TB>>>();
    deg_kernel<<<ecnt, TB>>>();
    invdeg_kernel<<<ncnt, TB>>>();

    // layer 1
    convw_kernel<<<wcnt, TB>>>(Wl[0], Wr[0]);
    zero_acc_kernel<<<zcnt, TB>>>();
    scatter_kernel<<<scnt, TB>>>(x0, 0);
    gemm_mma_kernel<<<ggrid, 512, SM_TOT>>>(x0, 0, nullptr, 1, bb[0], 1);

    // layer 2
    convw_kernel<<<wcnt, TB>>>(Wl[1], Wr[1]);
    zero_acc_kernel<<<zcnt, TB>>>();
    scatter_kernel<<<scnt, TB>>>(nullptr, 1);
    gemm_mma_kernel<<<ggrid, 512, SM_TOT>>>(nullptr, 1, nullptr, 2, bb[1], 1);

    // layer 3
    convw_kernel<<<wcnt, TB>>>(Wl[2], Wr[2]);
    zero_acc_kernel<<<zcnt, TB>>>();
    scatter_kernel<<<scnt, TB>>>(nullptr, 2);
    gemm_mma_kernel<<<ggrid, 512, SM_TOT>>>(nullptr, 2, out, 0, bb[2], 0);
}

// round 4
// speedup vs baseline: 2.7128x; 1.4651x over previous
#include <cuda_runtime.h>
#include <cuda_bf16.h>

#define NN 100000
#define DD 256
#define EE 300000
#define NB 98   // ceil(NN/1024)

typedef unsigned long long ull;

// ---------------- scratch ----------------
__device__ __align__(16) float g_acc[NN * DD];
__device__ __align__(16) float g_x1[NN * DD];
__device__ __align__(16) float g_x2[NN * DD];
__device__ int   g_degi[NN];
__device__ float g_invdeg[NN];
__device__ int   g_off[NN];
__device__ int   g_cursor[NN];
__device__ int   g_csr[EE];
__device__ int   g_src[EE];
__device__ int   g_dst[EE];
__device__ int   g_is64;
__device__ int   g_bsum[NB];
__device__ int   g_bsumex[NB];
__device__ __align__(16) __nv_bfloat16 g_bhi[256 * 512];  // W split hi: [m][k], k-major
__device__ __align__(16) __nv_bfloat16 g_blo[256 * 512];  // W split lo

// ---------------- index dtype detection + conversion ----------------
__global__ void detect_kernel(const unsigned int* __restrict__ w) {
    if (threadIdx.x == 0 && blockIdx.x == 0) {
        unsigned int s = 0;
        #pragma unroll 1
        for (int i = 1; i < 256; i += 2) s |= w[i];
        g_is64 = (s == 0u) ? 1 : 0;
    }
}

__global__ void convert_kernel(const void* __restrict__ edge) {
    int e = blockIdx.x * blockDim.x + threadIdx.x;
    if (e >= EE) return;
    if (g_is64) {
        const long long* p = (const long long*)edge;
        g_src[e] = (int)p[e];
        g_dst[e] = (int)p[EE + e];
    } else {
        const int* p = (const int*)edge;
        g_src[e] = p[e];
        g_dst[e] = p[EE + e];
    }
}

// ---------------- degree + CSR build ----------------
__global__ void zero_deg_kernel() {
    int n = blockIdx.x * blockDim.x + threadIdx.x;
    if (n < NN) g_degi[n] = 0;
}
__global__ void deg_kernel() {
    int e = blockIdx.x * blockDim.x + threadIdx.x;
    if (e < EE) atomicAdd(&g_degi[g_dst[e]], 1);
}
__global__ void invdeg_kernel() {
    int n = blockIdx.x * blockDim.x + threadIdx.x;
    if (n < NN) g_invdeg[n] = 1.0f / fmaxf((float)g_degi[n], 1.0f);
}

// block sums of degree (1024 per block)
__global__ void scanA_kernel() {
    __shared__ int sh[1024];
    int t = threadIdx.x;
    int n = blockIdx.x * 1024 + t;
    int v = (n < NN) ? g_degi[n] : 0;
    sh[t] = v;
    __syncthreads();
    #pragma unroll
    for (int off = 512; off > 0; off >>= 1) {
        if (t < off) sh[t] += sh[t + off];
        __syncthreads();
    }
    if (t == 0) g_bsum[blockIdx.x] = sh[0];
}

// exclusive scan of NB block sums (single thread; NB=98)
__global__ void scanB_kernel() {
    if (threadIdx.x == 0 && blockIdx.x == 0) {
        int acc = 0;
        for (int i = 0; i < NB; i++) {
            g_bsumex[i] = acc;
            acc += g_bsum[i];
        }
    }
}

// per-block exclusive scan + base -> offsets & cursors
__global__ void scanC_kernel() {
    __shared__ int sh[1024];
    int t = threadIdx.x;
    int n = blockIdx.x * 1024 + t;
    int v = (n < NN) ? g_degi[n] : 0;
    sh[t] = v;
    __syncthreads();
    #pragma unroll
    for (int off = 1; off < 1024; off <<= 1) {
        int x = (t >= off) ? sh[t - off] : 0;
        __syncthreads();
        sh[t] += x;
        __syncthreads();
    }
    if (n < NN) {
        int ex = g_bsumex[blockIdx.x] + sh[t] - v;
        g_off[n] = ex;
        g_cursor[n] = ex;
    }
}

__global__ void fill_kernel() {
    int e = blockIdx.x * blockDim.x + threadIdx.x;
    if (e >= EE) return;
    int pos = atomicAdd(&g_cursor[g_dst[e]], 1);
    g_csr[pos] = g_src[e];
}

// ---------------- aggregation: warp per node, CSR gather-sum ----------------
__global__ __launch_bounds__(256) void aggregate_kernel(const float* __restrict__ xext, int xsel) {
    const float* xin = (xsel == 0) ? xext : ((xsel == 1) ? g_x1 : g_x2);
    int warp = (blockIdx.x * blockDim.x + threadIdx.x) >> 5;
    if (warp >= NN) return;
    int lane = threadIdx.x & 31;
    int start = g_off[warp];
    int cnt = g_degi[warp];
    float4 a0 = make_float4(0.f, 0.f, 0.f, 0.f);
    float4 a1 = a0;
    #pragma unroll 1
    for (int i = 0; i < cnt; i++) {
        int s = g_csr[start + i];
        const float4* r = (const float4*)(xin + (size_t)s * DD);
        float4 v0 = r[lane];
        float4 v1 = r[lane + 32];
        a0.x += v0.x; a0.y += v0.y; a0.z += v0.z; a0.w += v0.w;
        a1.x += v1.x; a1.y += v1.y; a1.z += v1.z; a1.w += v1.w;
    }
    float4* o = (float4*)(g_acc + (size_t)warp * DD);
    o[lane] = a0;
    o[lane + 32] = a1;
}

// ---------------- weight split (fp32 -> bf16 hi/lo) ----------------
__global__ void convw_kernel(const float* __restrict__ Wl, const float* __restrict__ Wr) {
    int i = blockIdx.x * blockDim.x + threadIdx.x;
    if (i >= 256 * 512) return;
    int m = i >> 9, k = i & 511;
    float w = (k < 256) ? Wl[m * 256 + k] : Wr[m * 256 + (k - 256)];
    __nv_bfloat16 h = __float2bfloat16(w);
    float lo = w - __bfloat162float(h);
    g_bhi[i] = h;
    g_blo[i] = __float2bfloat16(lo);
}

// ---------------- mma helpers (baseline PTX, compiles at compute_103) ----------------
__device__ __forceinline__ unsigned sm_u32(const void* p) {
    unsigned r;
    asm("{ .reg .u64 t; cvta.to.shared.u64 t, %1; cvt.u32.u64 %0, t; }" : "=r"(r) : "l"(p));
    return r;
}
__device__ __forceinline__ void sts128(unsigned a, unsigned x, unsigned y, unsigned z, unsigned w) {
    asm volatile("st.shared.v4.b32 [%0], {%1,%2,%3,%4};" :: "r"(a), "r"(x), "r"(y), "r"(z), "r"(w));
}
__device__ __forceinline__ void ldsm4(unsigned& r0, unsigned& r1, unsigned& r2, unsigned& r3, unsigned a) {
    asm volatile("ldmatrix.sync.aligned.m8n8.x4.shared.b16 {%0,%1,%2,%3}, [%4];"
                 : "=r"(r0), "=r"(r1), "=r"(r2), "=r"(r3) : "r"(a));
}
__device__ __forceinline__ void mma16816(float* c, const unsigned* a, unsigned b0, unsigned b1) {
    asm volatile(
        "mma.sync.aligned.m16n8k16.row.col.f32.bf16.bf16.f32 "
        "{%0,%1,%2,%3}, {%4,%5,%6,%7}, {%8,%9}, {%0,%1,%2,%3};"
        : "+f"(c[0]), "+f"(c[1]), "+f"(c[2]), "+f"(c[3])
        : "r"(a[0]), "r"(a[1]), "r"(a[2]), "r"(a[3]), "r"(b0), "r"(b1));
}
__device__ __forceinline__ unsigned b2u(__nv_bfloat162 v) {
    unsigned r;
    memcpy(&r, &v, 4);
    return r;
}

// smem layout: rows padded to 80B (gcd(80,128)=16 -> conflict-free ldmatrix)
#define ASTR 80
#define SM_A 10240            // 128 rows * 80B
#define SM_B 20480            // 256 rows * 80B
#define SM_TOT (2*SM_A + 2*SM_B)   // AH | AL | BH | BL  = 61440 B

// ---------------- fused layer GEMM (mma.sync bf16, 2-term split) ----------------
__global__ __launch_bounds__(512) void gemm_mma_kernel(
    const float* __restrict__ xext, int xsel,
    float* __restrict__ oext, int osel,
    const float* __restrict__ bias, int do_relu)
{
    extern __shared__ char smem[];
    const float* xin = (xsel == 0) ? xext : ((xsel == 1) ? g_x1 : g_x2);
    float* out = (osel == 0) ? oext : ((osel == 1) ? g_x1 : g_x2);

    const unsigned su = sm_u32(smem);
    const unsigned suAH = su;
    const unsigned suAL = su + SM_A;
    const unsigned suBH = su + 2 * SM_A;
    const unsigned suBL = su + 2 * SM_A + SM_B;

    const int tid = threadIdx.x;
    const int wid = tid >> 5;
    const int lane = tid & 31;
    const int wm = wid & 1;
    const int wn = wid >> 1;
    const int row0 = blockIdx.x * 128;

    const int arow = tid >> 2;
    const int akq = tid & 3;
    const int gr = row0 + arow;
    const bool rok = gr < NN;
    const float invd = rok ? g_invdeg[gr] : 0.f;
    const float* aggrow = g_acc + (size_t)(rok ? gr : 0) * DD;
    const float* xrow = xin + (size_t)(rok ? gr : 0) * DD;

    const int brow = tid >> 1;
    const int bkh = (tid & 1) * 16;

    const unsigned aoff = (unsigned)((wm * 64 + (lane & 15)) * ASTR + (lane >> 4) * 16);
    const unsigned boff = (unsigned)((wn * 32 + ((lane >> 4) & 1) * 8 + (lane & 7)) * ASTR
                                     + ((lane >> 3) & 1) * 16);

    float acc[4][4][4];
    #pragma unroll
    for (int i = 0; i < 4; i++)
        #pragma unroll
        for (int j = 0; j < 4; j++)
            #pragma unroll
            for (int q = 0; q < 4; q++) acc[i][j][q] = 0.f;

    float4 pa0, pa1;
    uint4 pbh0, pbh1, pbl0, pbl1;
    float psc;

    auto loadCk = [&](int ck) {
        const int side = ck >> 3;
        const float* s = (side ? xrow : aggrow) + (ck & 7) * 32 + akq * 8;
        psc = side ? 1.f : invd;
        if (rok) {
            pa0 = *(const float4*)(s);
            pa1 = *(const float4*)(s + 4);
        } else {
            pa0 = make_float4(0.f, 0.f, 0.f, 0.f);
            pa1 = pa0;
        }
        size_t go = (size_t)brow * 512 + ck * 32 + bkh;
        pbh0 = *(const uint4*)(g_bhi + go);
        pbh1 = *(const uint4*)(g_bhi + go + 8);
        pbl0 = *(const uint4*)(g_blo + go);
        pbl1 = *(const uint4*)(g_blo + go + 8);
    };

    loadCk(0);

    #pragma unroll 1
    for (int ck = 0; ck < 16; ck++) {
        __syncthreads();
        {
            float v[8] = {pa0.x * psc, pa0.y * psc, pa0.z * psc, pa0.w * psc,
                          pa1.x * psc, pa1.y * psc, pa1.z * psc, pa1.w * psc};
            unsigned h[4], l[4];
            #pragma unroll
            for (int i = 0; i < 4; i++) {
                __nv_bfloat162 hh = __floats2bfloat162_rn(v[2 * i], v[2 * i + 1]);
                float lx = v[2 * i] - __bfloat162float(hh.x);
                float ly = v[2 * i + 1] - __bfloat162float(hh.y);
                __nv_bfloat162 ll = __floats2bfloat162_rn(lx, ly);
                h[i] = b2u(hh);
                l[i] = b2u(ll);
            }
            unsigned off = (unsigned)(arow * ASTR + akq * 16);
            sts128(suAH + off, h[0], h[1], h[2], h[3]);
            sts128(suAL + off, l[0], l[1], l[2], l[3]);
        }
        {
            unsigned off = (unsigned)(brow * ASTR + bkh * 2);
            sts128(suBH + off, pbh0.x, pbh0.y, pbh0.z, pbh0.w);
            sts128(suBH + off + 16, pbh1.x, pbh1.y, pbh1.z, pbh1.w);
            sts128(suBL + off, pbl0.x, pbl0.y, pbl0.z, pbl0.w);
            sts128(suBL + off + 16, pbl1.x, pbl1.y, pbl1.z, pbl1.w);
        }
        __syncthreads();
        if (ck < 15) loadCk(ck + 1);

        #pragma unroll
        for (int ks = 0; ks < 2; ks++) {
            const unsigned kb = (unsigned)(ks * 32);
            unsigned bh[4][2], bl[4][2];
            #pragma unroll
            for (int p = 0; p < 2; p++) {
                ldsm4(bh[2 * p][0], bh[2 * p][1], bh[2 * p + 1][0], bh[2 * p + 1][1],
                      suBH + boff + p * (16 * ASTR) + kb);
                ldsm4(bl[2 * p][0], bl[2 * p][1], bl[2 * p + 1][0], bl[2 * p + 1][1],
                      suBL + boff + p * (16 * ASTR) + kb);
            }
            #pragma unroll
            for (int mi = 0; mi < 4; mi++) {
                unsigned af[4];
                ldsm4(af[0], af[1], af[2], af[3], suAH + aoff + mi * (16 * ASTR) + kb);
                #pragma unroll
                for (int ni = 0; ni < 4; ni++) mma16816(acc[mi][ni], af, bh[ni][0], bh[ni][1]);
                #pragma unroll
                for (int ni = 0; ni < 4; ni++) mma16816(acc[mi][ni], af, bl[ni][0], bl[ni][1]);
                ldsm4(af[0], af[1], af[2], af[3], suAL + aoff + mi * (16 * ASTR) + kb);
                #pragma unroll
                for (int ni = 0; ni < 4; ni++) mma16816(acc[mi][ni], af, bh[ni][0], bh[ni][1]);
            }
        }
    }

    const int gr2 = lane >> 2;
    const int gc2 = (lane & 3) * 2;
    #pragma unroll
    for (int mi = 0; mi < 4; mi++) {
        const int rbase = row0 + wm * 64 + mi * 16 + gr2;
        #pragma unroll
        for (int h = 0; h < 2; h++) {
            const int r = rbase + h * 8;
            if (r < NN) {
                float* orow = out + (size_t)r * DD;
                #pragma unroll
                for (int ni = 0; ni < 4; ni++) {
                    const int c = wn * 32 + ni * 8 + gc2;
                    float2 bv = *(const float2*)(bias + c);
                    float v0 = acc[mi][ni][h * 2 + 0] + bv.x;
                    float v1 = acc[mi][ni][h * 2 + 1] + bv.y;
                    if (do_relu) { v0 = fmaxf(v0, 0.f); v1 = fmaxf(v1, 0.f); }
                    *(float2*)(orow + c) = make_float2(v0, v1);
                }
            }
        }
    }
}

// ---------------- launcher ----------------
extern "C" void kernel_launch(void* const* d_in, const int* in_sizes, int n_in,
                              void* d_out, int out_size) {
    (void)in_sizes; (void)n_in; (void)out_size;
    const void* edge = d_in[0];
    const float* x0 = (const float*)d_in[1];
    const float* Wl[3] = {(const float*)d_in[2], (const float*)d_in[5], (const float*)d_in[8]};
    const float* Wr[3] = {(const float*)d_in[3], (const float*)d_in[6], (const float*)d_in[9]};
    const float* bb[3] = {(const float*)d_in[4], (const float*)d_in[7], (const float*)d_in[10]};
    float* out = (float*)d_out;

    static int smem_set = 0;
    if (!smem_set) {
        cudaFuncSetAttribute(gemm_mma_kernel, cudaFuncAttributeMaxDynamicSharedMemorySize, SM_TOT);
        smem_set = 1;
    }

    const int TB = 256;
    const int ecnt = (EE + TB - 1) / TB;
    const int ncnt = (NN + TB - 1) / TB;
    const int wcnt = (256 * 512 + TB - 1) / TB;
    const int ggrid = (NN + 127) / 128;
    const int agrid = (NN * 32 + TB - 1) / TB;

    detect_kernel<<<1, 32>>>((const unsigned int*)edge);
    convert_kernel<<<ecnt, TB>>>(edge);
    zero_deg_kernel<<<ncnt, TB>>>();
    deg_kernel<<<ecnt, TB>>>();
    invdeg_kernel<<<ncnt, TB>>>();
    scanA_kernel<<<NB, 1024>>>();
    scanB_kernel<<<1, 32>>>();
    scanC_kernel<<<NB, 1024>>>();
    fill_kernel<<<ecnt, TB>>>();

    // layer 1
    convw_kernel<<<wcnt, TB>>>(Wl[0], Wr[0]);
    aggregate_kernel<<<agrid, TB>>>(x0, 0);
    gemm_mma_kernel<<<ggrid, 512, SM_TOT>>>(x0, 0, nullptr, 1, bb[0], 1);

    // layer 2
    convw_kernel<<<wcnt, TB>>>(Wl[1], Wr[1]);
    aggregate_kernel<<<agrid, TB>>>(nullptr, 1);
    gemm_mma_kernel<<<ggrid, 512, SM_TOT>>>(nullptr, 1, nullptr, 2, bb[1], 1);

    // layer 3
    convw_kernel<<<wcnt, TB>>>(Wl[2], Wr[2]);
    aggregate_kernel<<<agrid, TB>>>(nullptr, 2);
    gemm_mma_kernel<<<ggrid, 512, SM_TOT>>>(nullptr, 2, out, 0, bb[2], 0);
}

// round 5
// speedup vs baseline: 2.7362x; 1.0086x over previous
#include <cuda_runtime.h>
#include <cuda_bf16.h>

#define NN 100000
#define DD 256
#define EE 300000
#define NB 98   // ceil(NN/1024)

typedef unsigned long long ull;

// ---------------- scratch ----------------
__device__ __align__(16) float g_acc[NN * DD];
__device__ __align__(16) float g_x1[NN * DD];
__device__ __align__(16) float g_x2[NN * DD];
__device__ int   g_degi[NN];
__device__ float g_invdeg[NN];
__device__ int   g_off[NN];
__device__ int   g_cursor[NN];
__device__ int   g_csr[EE];
__device__ int   g_src[EE];
__device__ int   g_dst[EE];
__device__ int   g_is64;
__device__ int   g_bsum[NB];
__device__ int   g_bsumex[NB];
__device__ __align__(16) __nv_bfloat16 g_bhi[256 * 512];  // W split hi: [m][k], k-major
__device__ __align__(16) __nv_bfloat16 g_blo[256 * 512];  // W split lo

// ---------------- index dtype detection + conversion ----------------
__global__ void detect_kernel(const unsigned int* __restrict__ w) {
    if (threadIdx.x == 0 && blockIdx.x == 0) {
        unsigned int s = 0;
        #pragma unroll 1
        for (int i = 1; i < 256; i += 2) s |= w[i];
        g_is64 = (s == 0u) ? 1 : 0;
    }
}

__global__ void convert_kernel(const void* __restrict__ edge) {
    int e = blockIdx.x * blockDim.x + threadIdx.x;
    if (e >= EE) return;
    if (g_is64) {
        const long long* p = (const long long*)edge;
        g_src[e] = (int)p[e];
        g_dst[e] = (int)p[EE + e];
    } else {
        const int* p = (const int*)edge;
        g_src[e] = p[e];
        g_dst[e] = p[EE + e];
    }
}

// ---------------- degree + CSR build ----------------
__global__ void zero_deg_kernel() {
    int n = blockIdx.x * blockDim.x + threadIdx.x;
    if (n < NN) g_degi[n] = 0;
}
__global__ void deg_kernel() {
    int e = blockIdx.x * blockDim.x + threadIdx.x;
    if (e < EE) atomicAdd(&g_degi[g_dst[e]], 1);
}
__global__ void invdeg_kernel() {
    int n = blockIdx.x * blockDim.x + threadIdx.x;
    if (n < NN) g_invdeg[n] = 1.0f / fmaxf((float)g_degi[n], 1.0f);
}

__global__ void scanA_kernel() {
    __shared__ int sh[1024];
    int t = threadIdx.x;
    int n = blockIdx.x * 1024 + t;
    int v = (n < NN) ? g_degi[n] : 0;
    sh[t] = v;
    __syncthreads();
    #pragma unroll
    for (int off = 512; off > 0; off >>= 1) {
        if (t < off) sh[t] += sh[t + off];
        __syncthreads();
    }
    if (t == 0) g_bsum[blockIdx.x] = sh[0];
}

__global__ void scanB_kernel() {
    if (threadIdx.x == 0 && blockIdx.x == 0) {
        int acc = 0;
        for (int i = 0; i < NB; i++) {
            g_bsumex[i] = acc;
            acc += g_bsum[i];
        }
    }
}

__global__ void scanC_kernel() {
    __shared__ int sh[1024];
    int t = threadIdx.x;
    int n = blockIdx.x * 1024 + t;
    int v = (n < NN) ? g_degi[n] : 0;
    sh[t] = v;
    __syncthreads();
    #pragma unroll
    for (int off = 1; off < 1024; off <<= 1) {
        int x = (t >= off) ? sh[t - off] : 0;
        __syncthreads();
        sh[t] += x;
        __syncthreads();
    }
    if (n < NN) {
        int ex = g_bsumex[blockIdx.x] + sh[t] - v;
        g_off[n] = ex;
        g_cursor[n] = ex;
    }
}

__global__ void fill_kernel() {
    int e = blockIdx.x * blockDim.x + threadIdx.x;
    if (e >= EE) return;
    int pos = atomicAdd(&g_cursor[g_dst[e]], 1);
    g_csr[pos] = g_src[e];
}

// ---------------- aggregation: warp per node, CSR gather-sum ----------------
__global__ __launch_bounds__(256) void aggregate_kernel(const float* __restrict__ xext, int xsel) {
    const float* xin = (xsel == 0) ? xext : ((xsel == 1) ? g_x1 : g_x2);
    int warp = (blockIdx.x * blockDim.x + threadIdx.x) >> 5;
    if (warp >= NN) return;
    int lane = threadIdx.x & 31;
    int start = g_off[warp];
    int cnt = g_degi[warp];
    float4 a0 = make_float4(0.f, 0.f, 0.f, 0.f);
    float4 a1 = a0;
    #pragma unroll 1
    for (int i = 0; i < cnt; i++) {
        int s = g_csr[start + i];
        const float4* r = (const float4*)(xin + (size_t)s * DD);
        float4 v0 = r[lane];
        float4 v1 = r[lane + 32];
        a0.x += v0.x; a0.y += v0.y; a0.z += v0.z; a0.w += v0.w;
        a1.x += v1.x; a1.y += v1.y; a1.z += v1.z; a1.w += v1.w;
    }
    float4* o = (float4*)(g_acc + (size_t)warp * DD);
    o[lane] = a0;
    o[lane + 32] = a1;
}

// ---------------- weight split (fp32 -> bf16 hi/lo) ----------------
__global__ void convw_kernel(const float* __restrict__ Wl, const float* __restrict__ Wr) {
    int i = blockIdx.x * blockDim.x + threadIdx.x;
    if (i >= 256 * 512) return;
    int m = i >> 9, k = i & 511;
    float w = (k < 256) ? Wl[m * 256 + k] : Wr[m * 256 + (k - 256)];
    __nv_bfloat16 h = __float2bfloat16(w);
    float lo = w - __bfloat162float(h);
    g_bhi[i] = h;
    g_blo[i] = __float2bfloat16(lo);
}

// ---------------- mma / async-copy helpers (baseline PTX) ----------------
__device__ __forceinline__ unsigned sm_u32(const void* p) {
    unsigned r;
    asm("{ .reg .u64 t; cvta.to.shared.u64 t, %1; cvt.u32.u64 %0, t; }" : "=r"(r) : "l"(p));
    return r;
}
__device__ __forceinline__ void sts128(unsigned a, unsigned x, unsigned y, unsigned z, unsigned w) {
    asm volatile("st.shared.v4.b32 [%0], {%1,%2,%3,%4};" :: "r"(a), "r"(x), "r"(y), "r"(z), "r"(w));
}
__device__ __forceinline__ void cpasync16(unsigned smem, const void* g) {
    asm volatile("cp.async.cg.shared.global [%0], [%1], 16;" :: "r"(smem), "l"(g));
}
__device__ __forceinline__ void cpcommit() {
    asm volatile("cp.async.commit_group;");
}
__device__ __forceinline__ void cpwait0() {
    asm volatile("cp.async.wait_group 0;");
}
__device__ __forceinline__ void ldsm4(unsigned& r0, unsigned& r1, unsigned& r2, unsigned& r3, unsigned a) {
    asm volatile("ldmatrix.sync.aligned.m8n8.x4.shared.b16 {%0,%1,%2,%3}, [%4];"
                 : "=r"(r0), "=r"(r1), "=r"(r2), "=r"(r3) : "r"(a));
}
__device__ __forceinline__ void mma16816(float* c, const unsigned* a, unsigned b0, unsigned b1) {
    asm volatile(
        "mma.sync.aligned.m16n8k16.row.col.f32.bf16.bf16.f32 "
        "{%0,%1,%2,%3}, {%4,%5,%6,%7}, {%8,%9}, {%0,%1,%2,%3};"
        : "+f"(c[0]), "+f"(c[1]), "+f"(c[2]), "+f"(c[3])
        : "r"(a[0]), "r"(a[1]), "r"(a[2]), "r"(a[3]), "r"(b0), "r"(b1));
}
__device__ __forceinline__ unsigned b2u(__nv_bfloat162 v) {
    unsigned r;
    memcpy(&r, &v, 4);
    return r;
}

// smem layout: rows padded to 80B (gcd(80,128)=16 -> conflict-free ldmatrix)
#define ASTR 80
#define SM_A 10240             // 128 rows * 80B
#define SM_B 20480             // 256 rows * 80B
#define SM_STG (2*SM_A + 2*SM_B)    // one stage: AH|AL|BH|BL = 61440
#define SM_TOT (2*SM_STG)           // double buffered = 122880

// ---------------- fused layer GEMM (mma.sync bf16 2-term split, 2-stage pipeline) ----------------
// out[r, m] = relu?( sum_k A[r,k] * W[m,k] + b[m] ), A = [invdeg*acc | xin] (K=512)
__global__ __launch_bounds__(512) void gemm_mma_kernel(
    const float* __restrict__ xext, int xsel,
    float* __restrict__ oext, int osel,
    const float* __restrict__ bias, int do_relu)
{
    extern __shared__ char smem[];
    const float* xin = (xsel == 0) ? xext : ((xsel == 1) ? g_x1 : g_x2);
    float* out = (osel == 0) ? oext : ((osel == 1) ? g_x1 : g_x2);

    const unsigned su = sm_u32(smem);

    const int tid = threadIdx.x;
    const int wid = tid >> 5;
    const int lane = tid & 31;
    const int wm = wid & 1;
    const int wn = wid >> 1;
    const int row0 = blockIdx.x * 128;

    // A loader geometry
    const int arow = tid >> 2;
    const int akq = tid & 3;
    const int gr = row0 + arow;
    const bool rok = gr < NN;
    const float invd = rok ? g_invdeg[gr] : 0.f;
    const float* aggrow = g_acc + (size_t)(rok ? gr : 0) * DD;
    const float* xrow = xin + (size_t)(rok ? gr : 0) * DD;

    // B loader geometry (cp.async)
    const int brow = tid >> 1;
    const int bkh = (tid & 1) * 16;

    // ldmatrix fragment addresses (stage-relative)
    const unsigned aoff = (unsigned)((wm * 64 + (lane & 15)) * ASTR + (lane >> 4) * 16);
    const unsigned boff = (unsigned)((wn * 32 + ((lane >> 4) & 1) * 8 + (lane & 7)) * ASTR
                                     + ((lane >> 3) & 1) * 16);

    float acc[4][4][4];
    #pragma unroll
    for (int i = 0; i < 4; i++)
        #pragma unroll
        for (int j = 0; j < 4; j++)
            #pragma unroll
            for (int q = 0; q < 4; q++) acc[i][j][q] = 0.f;

    float4 pa0, pa1;   // prefetched A chunk (8 fp32)
    float psc;

    auto ldA = [&](int ck) {
        const int side = ck >> 3;
        const float* s = (side ? xrow : aggrow) + (ck & 7) * 32 + akq * 8;
        psc = side ? 1.f : invd;
        if (rok) {
            pa0 = *(const float4*)(s);
            pa1 = *(const float4*)(s + 4);
        } else {
            pa0 = make_float4(0.f, 0.f, 0.f, 0.f);
            pa1 = pa0;
        }
    };
    auto stsA = [&](int stg) {
        float v[8] = {pa0.x * psc, pa0.y * psc, pa0.z * psc, pa0.w * psc,
                      pa1.x * psc, pa1.y * psc, pa1.z * psc, pa1.w * psc};
        unsigned h[4], l[4];
        #pragma unroll
        for (int i = 0; i < 4; i++) {
            __nv_bfloat162 hh = __floats2bfloat162_rn(v[2 * i], v[2 * i + 1]);
            float lx = v[2 * i] - __bfloat162float(hh.x);
            float ly = v[2 * i + 1] - __bfloat162float(hh.y);
            __nv_bfloat162 ll = __floats2bfloat162_rn(lx, ly);
            h[i] = b2u(hh);
            l[i] = b2u(ll);
        }
        unsigned base = su + (unsigned)stg * SM_STG;
        unsigned off = (unsigned)(arow * ASTR + akq * 16);
        sts128(base + off, h[0], h[1], h[2], h[3]);
        sts128(base + SM_A + off, l[0], l[1], l[2], l[3]);
    };
    auto cpB = [&](int ck, int stg) {
        unsigned base = su + (unsigned)stg * SM_STG + 2 * SM_A;
        unsigned off = (unsigned)(brow * ASTR + bkh * 2);
        size_t go = (size_t)brow * 512 + ck * 32 + bkh;
        cpasync16(base + off, g_bhi + go);
        cpasync16(base + off + 16, g_bhi + go + 8);
        cpasync16(base + SM_B + off, g_blo + go);
        cpasync16(base + SM_B + off + 16, g_blo + go + 8);
        cpcommit();
    };

    // prologue: fill stage 0, prefetch A for chunk 1
    ldA(0);
    stsA(0);
    cpB(0, 0);
    ldA(1);

    #pragma unroll 1
    for (int ck = 0; ck < 16; ck++) {
        const int s = ck & 1;
        cpwait0();          // B[ck] arrived (only outstanding group)
        __syncthreads();    // A[ck] visible; all warps done reading buffer s^1

        if (ck < 15) {      // fill the other stage while computing
            stsA(s ^ 1);
            cpB(ck + 1, s ^ 1);
        }
        if (ck < 14) ldA(ck + 2);   // LDG latency hidden under MMA below

        const unsigned sbase = su + (unsigned)s * SM_STG;
        const unsigned suAH = sbase;
        const unsigned suAL = sbase + SM_A;
        const unsigned suBH = sbase + 2 * SM_A;
        const unsigned suBL = sbase + 2 * SM_A + SM_B;

        #pragma unroll
        for (int ks = 0; ks < 2; ks++) {
            const unsigned kb = (unsigned)(ks * 32);
            unsigned bh[4][2], bl[4][2];
            #pragma unroll
            for (int p = 0; p < 2; p++) {
                ldsm4(bh[2 * p][0], bh[2 * p][1], bh[2 * p + 1][0], bh[2 * p + 1][1],
                      suBH + boff + p * (16 * ASTR) + kb);
                ldsm4(bl[2 * p][0], bl[2 * p][1], bl[2 * p + 1][0], bl[2 * p + 1][1],
                      suBL + boff + p * (16 * ASTR) + kb);
            }
            #pragma unroll
            for (int mi = 0; mi < 4; mi++) {
                unsigned af[4];
                ldsm4(af[0], af[1], af[2], af[3], suAH + aoff + mi * (16 * ASTR) + kb);
                #pragma unroll
                for (int ni = 0; ni < 4; ni++) mma16816(acc[mi][ni], af, bh[ni][0], bh[ni][1]);
                #pragma unroll
                for (int ni = 0; ni < 4; ni++) mma16816(acc[mi][ni], af, bl[ni][0], bl[ni][1]);
                ldsm4(af[0], af[1], af[2], af[3], suAL + aoff + mi * (16 * ASTR) + kb);
                #pragma unroll
                for (int ni = 0; ni < 4; ni++) mma16816(acc[mi][ni], af, bh[ni][0], bh[ni][1]);
            }
        }
    }

    // ---- epilogue: bias + relu, direct gmem stores ----
    const int gr2 = lane >> 2;
    const int gc2 = (lane & 3) * 2;
    #pragma unroll
    for (int mi = 0; mi < 4; mi++) {
        const int rbase = row0 + wm * 64 + mi * 16 + gr2;
        #pragma unroll
        for (int h = 0; h < 2; h++) {
            const int r = rbase + h * 8;
            if (r < NN) {
                float* orow = out + (size_t)r * DD;
                #pragma unroll
                for (int ni = 0; ni < 4; ni++) {
                    const int c = wn * 32 + ni * 8 + gc2;
                    float2 bv = *(const float2*)(bias + c);
                    float v0 = acc[mi][ni][h * 2 + 0] + bv.x;
                    float v1 = acc[mi][ni][h * 2 + 1] + bv.y;
                    if (do_relu) { v0 = fmaxf(v0, 0.f); v1 = fmaxf(v1, 0.f); }
                    *(float2*)(orow + c) = make_float2(v0, v1);
                }
            }
        }
    }
}

// ---------------- launcher ----------------
extern "C" void kernel_launch(void* const* d_in, const int* in_sizes, int n_in,
                              void* d_out, int out_size) {
    (void)in_sizes; (void)n_in; (void)out_size;
    const void* edge = d_in[0];
    const float* x0 = (const float*)d_in[1];
    const float* Wl[3] = {(const float*)d_in[2], (const float*)d_in[5], (const float*)d_in[8]};
    const float* Wr[3] = {(const float*)d_in[3], (const float*)d_in[6], (const float*)d_in[9]};
    const float* bb[3] = {(const float*)d_in[4], (const float*)d_in[7], (const float*)d_in[10]};
    float* out = (float*)d_out;

    static int smem_set = 0;
    if (!smem_set) {
        cudaFuncSetAttribute(gemm_mma_kernel, cudaFuncAttributeMaxDynamicSharedMemorySize, SM_TOT);
        smem_set = 1;
    }

    const int TB = 256;
    const int ecnt = (EE + TB - 1) / TB;
    const int ncnt = (NN + TB - 1) / TB;
    const int wcnt = (256 * 512 + TB - 1) / TB;
    const int ggrid = (NN + 127) / 128;
    const int agrid = (NN * 32 + TB - 1) / TB;

    detect_kernel<<<1, 32>>>((const unsigned int*)edge);
    convert_kernel<<<ecnt, TB>>>(edge);
    zero_deg_kernel<<<ncnt, TB>>>();
    deg_kernel<<<ecnt, TB>>>();
    invdeg_kernel<<<ncnt, TB>>>();
    scanA_kernel<<<NB, 1024>>>();
    scanB_kernel<<<1, 32>>>();
    scanC_kernel<<<NB, 1024>>>();
    fill_kernel<<<ecnt, TB>>>();

    // layer 1
    convw_kernel<<<wcnt, TB>>>(Wl[0], Wr[0]);
    aggregate_kernel<<<agrid, TB>>>(x0, 0);
    gemm_mma_kernel<<<ggrid, 512, SM_TOT>>>(x0, 0, nullptr, 1, bb[0], 1);

    // layer 2
    convw_kernel<<<wcnt, TB>>>(Wl[1], Wr[1]);
    aggregate_kernel<<<agrid, TB>>>(nullptr, 1);
    gemm_mma_kernel<<<ggrid, 512, SM_TOT>>>(nullptr, 1, nullptr, 2, bb[1], 1);

    // layer 3
    convw_kernel<<<wcnt, TB>>>(Wl[2], Wr[2]);
    aggregate_kernel<<<agrid, TB>>>(nullptr, 2);
    gemm_mma_kernel<<<ggrid, 512, SM_TOT>>>(nullptr, 2, out, 0, bb[2], 0);
}